// round 16
// baseline (speedup 1.0000x reference)
#include <cuda_runtime.h>
#include <cuda_bf16.h>
#include <float.h>
#include <math.h>

#define NN   2048
#define BBATCH 4
#define SS   1024
#define SFZ  384
#define IFZ  256
#define HH   8
#define AA   64
#define HA   512
#define MAXT 36

typedef unsigned long long ull;
typedef unsigned int u32;
typedef unsigned short u16;

__device__ __align__(16) float g_q[NN * HA];
__device__ __align__(16) float g_gate[NN * HA];
__device__ __align__(16) float g_v[BBATCH * SS * HA];
__device__ __align__(16) float g_y[NN * IFZ];
__device__ __align__(16) unsigned char g_mask[BBATCH * SS];
__device__ int g_tb[MAXT], g_ts[MAXT], g_tc[MAXT], g_nt;
__device__ __align__(16) __nv_bfloat16 g_kh[BBATCH * SS * HA];
__device__ __align__(16) __nv_bfloat16 g_kl[BBATCH * SS * HA];
__device__ __align__(16) __nv_bfloat16 g_vh[BBATCH * HH * AA * SS];
__device__ __align__(16) __nv_bfloat16 g_vl[BBATCH * HH * AA * SS];
__device__ __align__(16) float g_sc0[NN * SS];
__device__ __align__(16) float g_sc1[NN * SS];
__device__ __align__(16) __nv_bfloat16 g_eh[BBATCH * SS * SFZ];
__device__ __align__(16) __nv_bfloat16 g_el[BBATCH * SS * SFZ];
__device__ __align__(16) __nv_bfloat16 g_wht[2 * HA * SFZ];
__device__ __align__(16) __nv_bfloat16 g_wlt[2 * HA * SFZ];
__device__ __align__(16) __nv_bfloat16 g_xh[NN * IFZ];
__device__ __align__(16) __nv_bfloat16 g_xl[NN * IFZ];
__device__ __align__(16) __nv_bfloat16 g_qgh[2 * HA * IFZ];
__device__ __align__(16) __nv_bfloat16 g_qgl[2 * HA * IFZ];
__device__ __align__(16) __nv_bfloat16 g_fh[NN * HA];
__device__ __align__(16) __nv_bfloat16 g_fl[NN * HA];
__device__ __align__(16) __nv_bfloat16 g_wbh[IFZ * HA];
__device__ __align__(16) __nv_bfloat16 g_wbl[IFZ * HA];

// ---- bf16 split helpers ----
__device__ __forceinline__ u32 pkbf(float a, float b) {
    __nv_bfloat162 t = __float22bfloat162_rn(make_float2(a, b));
    return *(u32*)&t;
}
__device__ __forceinline__ float2 unbf(u32 h) {
    return __bfloat1622float2(*(__nv_bfloat162*)&h);
}

// ---- ldmatrix + mma.sync ----
static __device__ __forceinline__ u32 s2u(const void* p) {
    u32 a; asm("{.reg .u64 t; cvta.to.shared.u64 t, %1; cvt.u32.u64 %0, t;}" : "=r"(a) : "l"(p));
    return a;
}
__device__ __forceinline__ void ldmx4(u32* r, u32 a) {
    asm volatile("ldmatrix.sync.aligned.m8n8.x4.shared.b16 {%0,%1,%2,%3},[%4];"
                 : "=r"(r[0]), "=r"(r[1]), "=r"(r[2]), "=r"(r[3]) : "r"(a));
}
__device__ __forceinline__ void ldmx2(u32* r, u32 a) {
    asm volatile("ldmatrix.sync.aligned.m8n8.x2.shared.b16 {%0,%1},[%2];"
                 : "=r"(r[0]), "=r"(r[1]) : "r"(a));
}
__device__ __forceinline__ void mma16816(float* d, const u32* a, const u32* bb) {
    asm volatile("mma.sync.aligned.m16n8k16.row.col.f32.bf16.bf16.f32 "
                 "{%0,%1,%2,%3},{%4,%5,%6,%7},{%8,%9},{%0,%1,%2,%3};"
                 : "+f"(d[0]), "+f"(d[1]), "+f"(d[2]), "+f"(d[3])
                 : "r"(a[0]), "r"(a[1]), "r"(a[2]), "r"(a[3]), "r"(bb[0]), "r"(bb[1]));
}

// attn smem layout
#define O_QH 0
#define O_QL 9216
#define O_SC 0
#define O_AL 17408
#define O_B0 18432
#define O_B1 55296
#define ATTN_SMEMB 92160
// GEMM double-buffer smem
#define GEMM_SMEMB 73728

// ---------------- prep ------------------------------------------------------
__global__ void prep_k(const void* mask_in, const void* batch_in) {
    __shared__ int flg[2];
    __shared__ int cnt[BBATCH];
    int tid = threadIdx.x;
    if (tid < 2) flg[tid] = 0;
    if (tid < BBATCH) cnt[tid] = 0;
    __syncthreads();
    const unsigned int* bw = (const unsigned int*)batch_in;
    unsigned int o = 0;
    for (int i = tid * 2 + 1; i < NN; i += blockDim.x * 2) o |= bw[i];
    if (o) atomicOr(&flg[0], 1);
    const unsigned char* mb = (const unsigned char*)mask_in;
    int f = 0;
    for (int i = tid; i < BBATCH * SS; i += blockDim.x)
        if ((i & 3) && mb[i]) f = 1;
    if (f) atomicOr(&flg[1], 1);
    __syncthreads();
    int is32 = flg[0], isb = flg[1];
    int lc[BBATCH] = {0, 0, 0, 0};
    for (int i = tid; i < NN; i += blockDim.x) {
        int v = is32 ? ((const int*)batch_in)[i]
                     : (int)((const long long*)batch_in)[i];
        lc[v & 3]++;
    }
    #pragma unroll
    for (int b = 0; b < BBATCH; b++) if (lc[b]) atomicAdd(&cnt[b], lc[b]);
    for (int i = tid; i < BBATCH * SS; i += blockDim.x)
        g_mask[i] = isb ? (mb[i] ? 1 : 0) : (((const int*)mask_in)[i] ? 1 : 0);
    __syncthreads();
    if (tid == 0) {
        int st = 0, t = 0;
        for (int b = 0; b < BBATCH; b++) {
            int e = st + cnt[b];
            for (int s = st; s < e; s += 64) {
                g_tb[t] = b; g_ts[t] = s; g_tc[t] = min(64, e - s); t++;
            }
            st = e;
        }
        g_nt = t;
    }
}

// ---------------- emb + x -> bf16 hi/lo (merged) ---------------------------
__global__ void conv_ex_k(const float* __restrict__ emb, const float* __restrict__ x) {
    int bid = blockIdx.x;
    const float* src;
    __nv_bfloat16 *oh, *ol;
    size_t i;
    if (bid < 1536) {
        src = emb; oh = g_eh; ol = g_el;
        i = ((size_t)bid * 256 + threadIdx.x) * 4;
    } else {
        src = x; oh = g_xh; ol = g_xl;
        i = ((size_t)(bid - 1536) * 256 + threadIdx.x) * 4;
    }
    float4 v = *(const float4*)&src[i];
    u32 h0 = pkbf(v.x, v.y), h1 = pkbf(v.z, v.w);
    float2 f0 = unbf(h0), f1 = unbf(h1);
    u32 l0 = pkbf(v.x - f0.x, v.y - f0.y), l1 = pkbf(v.z - f1.x, v.w - f1.y);
    *(uint2*)&oh[i] = make_uint2(h0, h1);
    *(uint2*)&ol[i] = make_uint2(l0, l1);
}

// ---------------- all weight transposers (merged) --------------------------
__global__ void __launch_bounds__(128) conv_allw_k(const float* __restrict__ Wk,
                                                   const float* __restrict__ Wv,
                                                   const float* __restrict__ Wq,
                                                   const float* __restrict__ Wg,
                                                   const float* __restrict__ Wb) {
    __shared__ float buf[64 * 68];
    int z = blockIdx.z;
    int ktiles = (z == 0) ? 6 : (z == 1) ? 4 : 8;
    int ntiles = (z == 2) ? 4 : 16;
    if ((int)blockIdx.x >= ktiles || (int)blockIdx.y >= ntiles) return;
    int kc = blockIdx.x * 64, ng = blockIdx.y * 64;
    const float* W; int srcS, outS, nb;
    __nv_bfloat16 *oh, *ol;
    if (z == 0) { W = (ng < HA) ? Wk : Wv; nb = ng & (HA - 1); srcS = HA; outS = SFZ; oh = g_wht; ol = g_wlt; }
    else if (z == 1) { W = (ng < HA) ? Wq : Wg; nb = ng & (HA - 1); srcS = HA; outS = IFZ; oh = g_qgh; ol = g_qgl; }
    else { W = Wb; nb = ng; srcS = IFZ; outS = HA; oh = g_wbh; ol = g_wbl; }
    int tid = threadIdx.x;
    #pragma unroll
    for (int p = 0; p < 8; p++) {
        int idx = tid + p * 128, kk = idx >> 4, nn = (idx & 15) * 4;
        *(float4*)&buf[kk * 68 + nn] =
            *(const float4*)&W[(size_t)(kc + kk) * srcS + nb + nn];
    }
    __syncthreads();
    int nn = tid >> 1, kh = (tid & 1) * 32;
    u32 hv[16], lv[16];
    #pragma unroll
    for (int p = 0; p < 16; p++) {
        float x0 = buf[(kh + 2 * p) * 68 + nn], x1 = buf[(kh + 2 * p + 1) * 68 + nn];
        hv[p] = pkbf(x0, x1);
        float2 f = unbf(hv[p]);
        lv[p] = pkbf(x0 - f.x, x1 - f.y);
    }
    size_t o = (size_t)(ng + nn) * outS + kc + kh;
    #pragma unroll
    for (int p = 0; p < 4; p++) {
        *(uint4*)&oh[o + p * 8] = make_uint4(hv[4*p], hv[4*p+1], hv[4*p+2], hv[4*p+3]);
        *(uint4*)&ol[o + p * 8] = make_uint4(lv[4*p], lv[4*p+1], lv[4*p+2], lv[4*p+3]);
    }
}

// ---------------- q,gate = x @ Wq/Wg : mma 3-term, double-buffered ---------
__global__ void __launch_bounds__(128) proj_qg_mma(const float* __restrict__ bg) {
    extern __shared__ __align__(16) unsigned char smd[];
    const u32 SB = s2u(smd);
    int m0 = blockIdx.x * 64, ng = blockIdx.y * 64;
    int tid = threadIdx.x, lane = tid & 31, w = tid >> 5;
    const int lr = lane & 15;
    const u32 brow = lr & 7, bc8 = (lr >> 3) * 8;
    const int r0 = 16 * w + (lane >> 2), cc0 = (lane & 3) * 2;
    u32 arow = 16 * w + (lane & 7) + ((lane >> 3) & 1) * 8;
    u32 acol = ((lane >> 4) & 1) * 8;
    float acc[8][4];
    #pragma unroll
    for (int cg = 0; cg < 8; cg++)
        acc[cg][0] = acc[cg][1] = acc[cg][2] = acc[cg][3] = 0.f;
    int r = tid >> 1, kh2 = (tid & 1) * 32;
    const u32 ro = (u32)(r * 72 + kh2) * 2;
    size_t xa = (size_t)(m0 + r) * IFZ + kh2;
    size_t wa = (size_t)(ng + r) * IFZ + kh2;
    #pragma unroll
    for (int u = 0; u < 4; u++) {
        *(uint4*)(smd + 0     + ro + u * 16) = *(const uint4*)(&g_xh[xa] + u * 8);
        *(uint4*)(smd + 9216  + ro + u * 16) = *(const uint4*)(&g_xl[xa] + u * 8);
        *(uint4*)(smd + 18432 + ro + u * 16) = *(const uint4*)(&g_qgh[wa] + u * 8);
        *(uint4*)(smd + 27648 + ro + u * 16) = *(const uint4*)(&g_qgl[wa] + u * 8);
    }
    __syncthreads();
    for (int kc = 0; kc < 4; kc++) {
        u32 bb = (kc & 1) ? 36864 : 0, bn = (kc & 1) ? 0 : 36864;
        uint4 pf[16];
        if (kc < 3) {
            int k0 = (kc + 1) * 64;
            #pragma unroll
            for (int u = 0; u < 4; u++) {
                pf[u]      = *(const uint4*)(&g_xh[xa + k0] + u * 8);
                pf[u + 4]  = *(const uint4*)(&g_xl[xa + k0] + u * 8);
                pf[u + 8]  = *(const uint4*)(&g_qgh[wa + k0] + u * 8);
                pf[u + 12] = *(const uint4*)(&g_qgl[wa + k0] + u * 8);
            }
        }
        u32 ahf[4][4], alf[4][4];
        #pragma unroll
        for (int k = 0; k < 4; k++) {
            ldmx4(ahf[k], SB + bb + 0    + (arow * 72 + acol + 16 * k) * 2);
            ldmx4(alf[k], SB + bb + 9216 + (arow * 72 + acol + 16 * k) * 2);
        }
        #pragma unroll
        for (int cg = 0; cg < 8; cg++) {
            #pragma unroll
            for (int k = 0; k < 4; k++) {
                u32 off = ((cg * 8 + brow) * 72 + 16 * k + bc8) * 2;
                u32 bh[2], bl[2];
                ldmx2(bh, SB + bb + 18432 + off);
                ldmx2(bl, SB + bb + 27648 + off);
                mma16816(acc[cg], ahf[k], bh);
                mma16816(acc[cg], ahf[k], bl);
                mma16816(acc[cg], alf[k], bh);
            }
        }
        if (kc < 3) {
            #pragma unroll
            for (int u = 0; u < 4; u++) {
                *(uint4*)(smd + bn + 0     + ro + u * 16) = pf[u];
                *(uint4*)(smd + bn + 9216  + ro + u * 16) = pf[u + 4];
                *(uint4*)(smd + bn + 18432 + ro + u * 16) = pf[u + 8];
                *(uint4*)(smd + bn + 27648 + ro + u * 16) = pf[u + 12];
            }
        }
        __syncthreads();
    }
    bool isg = (ng >= HA);
    int nc0 = ng & (HA - 1);
    if (isg) {
        #pragma unroll
        for (int cg = 0; cg < 8; cg++) {
            int c = nc0 + cg * 8 + cc0;
            float b0 = bg[c], b1 = bg[c + 1];
            float2 o0, o1;
            o0.x = 1.0f / (1.0f + __expf(-(acc[cg][0] + b0)));
            o0.y = 1.0f / (1.0f + __expf(-(acc[cg][1] + b1)));
            o1.x = 1.0f / (1.0f + __expf(-(acc[cg][2] + b0)));
            o1.y = 1.0f / (1.0f + __expf(-(acc[cg][3] + b1)));
            *(float2*)&g_gate[(size_t)(m0 + r0) * HA + c] = o0;
            *(float2*)&g_gate[(size_t)(m0 + r0 + 8) * HA + c] = o1;
        }
    } else {
        #pragma unroll
        for (int cg = 0; cg < 8; cg++) {
            int c = nc0 + cg * 8 + cc0;
            *(float2*)&g_q[(size_t)(m0 + r0) * HA + c] = make_float2(acc[cg][0], acc[cg][1]);
            *(float2*)&g_q[(size_t)(m0 + r0 + 8) * HA + c] = make_float2(acc[cg][2], acc[cg][3]);
        }
    }
}

// ---------------- k,v = emb @ Wk/Wv : mma 3-term, double-buffered ----------
__global__ void __launch_bounds__(128) proj_kv_mma() {
    extern __shared__ __align__(16) unsigned char smd[];
    const u32 SB = s2u(smd);
    int m0 = blockIdx.x * 64, ng = blockIdx.y * 64;
    int tid = threadIdx.x, lane = tid & 31, w = tid >> 5;
    const int lr = lane & 15;
    const u32 brow = lr & 7, bc8 = (lr >> 3) * 8;
    const int r0 = 16 * w + (lane >> 2), cc0 = (lane & 3) * 2;
    u32 arow = 16 * w + (lane & 7) + ((lane >> 3) & 1) * 8;
    u32 acol = ((lane >> 4) & 1) * 8;
    float acc[8][4];
    #pragma unroll
    for (int cg = 0; cg < 8; cg++)
        acc[cg][0] = acc[cg][1] = acc[cg][2] = acc[cg][3] = 0.f;
    int r = tid >> 1, kh2 = (tid & 1) * 32;
    const u32 ro = (u32)(r * 72 + kh2) * 2;
    size_t ea = (size_t)(m0 + r) * SFZ + kh2;
    size_t wa = (size_t)(ng + r) * SFZ + kh2;
    #pragma unroll
    for (int u = 0; u < 4; u++) {
        *(uint4*)(smd + 0     + ro + u * 16) = *(const uint4*)(&g_eh[ea] + u * 8);
        *(uint4*)(smd + 9216  + ro + u * 16) = *(const uint4*)(&g_el[ea] + u * 8);
        *(uint4*)(smd + 18432 + ro + u * 16) = *(const uint4*)(&g_wht[wa] + u * 8);
        *(uint4*)(smd + 27648 + ro + u * 16) = *(const uint4*)(&g_wlt[wa] + u * 8);
    }
    __syncthreads();
    for (int kc = 0; kc < 6; kc++) {
        u32 bb = (kc & 1) ? 36864 : 0, bn = (kc & 1) ? 0 : 36864;
        uint4 pf[16];
        if (kc < 5) {
            int k0 = (kc + 1) * 64;
            #pragma unroll
            for (int u = 0; u < 4; u++) {
                pf[u]      = *(const uint4*)(&g_eh[ea + k0] + u * 8);
                pf[u + 4]  = *(const uint4*)(&g_el[ea + k0] + u * 8);
                pf[u + 8]  = *(const uint4*)(&g_wht[wa + k0] + u * 8);
                pf[u + 12] = *(const uint4*)(&g_wlt[wa + k0] + u * 8);
            }
        }
        u32 ahf[4][4], alf[4][4];
        #pragma unroll
        for (int k = 0; k < 4; k++) {
            ldmx4(ahf[k], SB + bb + 0    + (arow * 72 + acol + 16 * k) * 2);
            ldmx4(alf[k], SB + bb + 9216 + (arow * 72 + acol + 16 * k) * 2);
        }
        #pragma unroll
        for (int cg = 0; cg < 8; cg++) {
            #pragma unroll
            for (int k = 0; k < 4; k++) {
                u32 off = ((cg * 8 + brow) * 72 + 16 * k + bc8) * 2;
                u32 bh[2], bl[2];
                ldmx2(bh, SB + bb + 18432 + off);
                ldmx2(bl, SB + bb + 27648 + off);
                mma16816(acc[cg], ahf[k], bh);
                mma16816(acc[cg], ahf[k], bl);
                mma16816(acc[cg], alf[k], bh);
            }
        }
        if (kc < 5) {
            #pragma unroll
            for (int u = 0; u < 4; u++) {
                *(uint4*)(smd + bn + 0     + ro + u * 16) = pf[u];
                *(uint4*)(smd + bn + 9216  + ro + u * 16) = pf[u + 4];
                *(uint4*)(smd + bn + 18432 + ro + u * 16) = pf[u + 8];
                *(uint4*)(smd + bn + 27648 + ro + u * 16) = pf[u + 12];
            }
        }
        __syncthreads();
    }
    bool isv = (ng >= HA);
    int nc0 = ng & (HA - 1);
    if (isv) {
        #pragma unroll
        for (int cg = 0; cg < 8; cg++) {
            int c = nc0 + cg * 8 + cc0;
            *(float2*)&g_v[(size_t)(m0 + r0) * HA + c] = make_float2(acc[cg][0], acc[cg][1]);
            *(float2*)&g_v[(size_t)(m0 + r0 + 8) * HA + c] = make_float2(acc[cg][2], acc[cg][3]);
        }
    } else {
        #pragma unroll
        for (int cg = 0; cg < 8; cg++) {
            int c = nc0 + cg * 8 + cc0;
            u32 h0 = pkbf(acc[cg][0], acc[cg][1]);
            u32 h1 = pkbf(acc[cg][2], acc[cg][3]);
            float2 f0 = unbf(h0), f1 = unbf(h1);
            u32 l0 = pkbf(acc[cg][0] - f0.x, acc[cg][1] - f0.y);
            u32 l1 = pkbf(acc[cg][2] - f1.x, acc[cg][3] - f1.y);
            *(u32*)&g_kh[(size_t)(m0 + r0) * HA + c] = h0;
            *(u32*)&g_kl[(size_t)(m0 + r0) * HA + c] = l0;
            *(u32*)&g_kh[(size_t)(m0 + r0 + 8) * HA + c] = h1;
            *(u32*)&g_kl[(size_t)(m0 + r0 + 8) * HA + c] = l1;
        }
    }
}

// ---------------- V -> transposed [b][h][a][s] bf16 hi/lo ------------------
__global__ void __launch_bounds__(128) conv_v_k() {
    __shared__ float buf[64 * 68];
    int b = blockIdx.z, h = blockIdx.y, s0 = blockIdx.x * 64;
    int tid = threadIdx.x;
    #pragma unroll
    for (int p = 0; p < 8; p++) {
        int idx = tid + p * 128, s = idx >> 4, q = idx & 15;
        *(float4*)&buf[s * 68 + q * 4] =
            *(const float4*)&g_v[((size_t)(b << 10) + s0 + s) * HA + h * AA + q * 4];
    }
    __syncthreads();
    int aa = tid >> 1, sh = (tid & 1) * 32;
    u32 hv[16], lv[16];
    #pragma unroll
    for (int p = 0; p < 16; p++) {
        float x0 = buf[(sh + 2 * p) * 68 + aa], x1 = buf[(sh + 2 * p + 1) * 68 + aa];
        hv[p] = pkbf(x0, x1);
        float2 f = unbf(hv[p]);
        lv[p] = pkbf(x0 - f.x, x1 - f.y);
    }
    size_t o = ((size_t)(b * HH + h) * AA + aa) * SS + s0 + sh;
    #pragma unroll
    for (int p = 0; p < 4; p++) {
        *(uint4*)&g_vh[o + p * 8] = make_uint4(hv[4*p], hv[4*p+1], hv[4*p+2], hv[4*p+3]);
        *(uint4*)&g_vl[o + p * 8] = make_uint4(lv[4*p], lv[4*p+1], lv[4*p+2], lv[4*p+3]);
    }
}

// ---------------- attention: reg-resident flash + double-buffered staging --
__global__ void __launch_bounds__(128) attn_mma() {
    extern __shared__ unsigned char sm8[];
    const int t = blockIdx.x;
    if (t >= g_nt) return;
    const int h = blockIdx.y;
    const int b = g_tb[t], n0 = g_ts[t], cnt = g_tc[t];
    const int tid = threadIdx.x, lane = tid & 31, w = tid >> 5;
    const u32 SB = s2u(sm8);
    float* Sc = (float*)(sm8 + O_SC);
    float* Al = (float*)(sm8 + O_AL);
    const int jr = tid >> 1, half = (tid & 1) * 32;
    const u32 ro = (u32)(jr * 72 + half) * 2;
    const size_t krb = ((size_t)(b << 10) + jr) * HA + h * AA + half;
    const size_t vrb = ((size_t)(b * HH + h) * AA + jr) * SS + half;

    {
        bool val = jr < cnt;
        const float* q = &g_q[(size_t)(n0 + jr) * HA + h * AA + half];
        #pragma unroll
        for (int u = 0; u < 4; u++) {
            float4 x0 = val ? *(const float4*)(q + u * 8) : make_float4(0, 0, 0, 0);
            float4 x1 = val ? *(const float4*)(q + u * 8 + 4) : make_float4(0, 0, 0, 0);
            u32 h0 = pkbf(x0.x, x0.y), h1 = pkbf(x0.z, x0.w);
            u32 h2 = pkbf(x1.x, x1.y), h3 = pkbf(x1.z, x1.w);
            float2 f0 = unbf(h0), f1 = unbf(h1), f2 = unbf(h2), f3 = unbf(h3);
            u32 l0 = pkbf(x0.x - f0.x, x0.y - f0.y), l1 = pkbf(x0.z - f1.x, x0.w - f1.y);
            u32 l2 = pkbf(x1.x - f2.x, x1.y - f2.y), l3 = pkbf(x1.z - f3.x, x1.w - f3.y);
            *(uint4*)(sm8 + O_QH + ro + u * 16) = make_uint4(h0, h1, h2, h3);
            *(uint4*)(sm8 + O_QL + ro + u * 16) = make_uint4(l0, l1, l2, l3);
        }
    }
    __syncthreads();
    u32 qhf[4][4], qlf[4][4];
    {
        u32 arow = 16 * w + (lane & 7) + ((lane >> 3) & 1) * 8;
        u32 acol = ((lane >> 4) & 1) * 8;
        #pragma unroll
        for (int k = 0; k < 4; k++) {
            ldmx4(qhf[k], SB + O_QH + (arow * 72 + acol + 16 * k) * 2);
            ldmx4(qlf[k], SB + O_QL + (arow * 72 + acol + 16 * k) * 2);
        }
    }
    __syncthreads();

    #pragma unroll
    for (int u = 0; u < 4; u++) {
        *(uint4*)(sm8 + O_B0 + 0     + ro + u * 16) = *(const uint4*)(&g_kh[krb] + u * 8);
        *(uint4*)(sm8 + O_B0 + 9216  + ro + u * 16) = *(const uint4*)(&g_kl[krb] + u * 8);
        *(uint4*)(sm8 + O_B0 + 18432 + ro + u * 16) = *(const uint4*)(&g_vh[vrb] + u * 8);
        *(uint4*)(sm8 + O_B0 + 27648 + ro + u * 16) = *(const uint4*)(&g_vl[vrb] + u * 8);
    }
    __syncthreads();

    const int lr = lane & 15;
    const u32 brow = lr & 7, bc8 = (lr >> 3) * 8;
    const int r0 = 16 * w + (lane >> 2), cc0 = (lane & 3) * 2;
    float mo0 = -FLT_MAX, mo1 = -FLT_MAX, ls0 = 0.f, ls1 = 0.f;
    float feat[8][4];
    #pragma unroll
    for (int cg = 0; cg < 8; cg++)
        feat[cg][0] = feat[cg][1] = feat[cg][2] = feat[cg][3] = 0.f;

    for (int c = 0; c < 16; c++) {
        int s0 = c * 64;
        u32 bb = (c & 1) ? O_B1 : O_B0;
        u32 bn = (c & 1) ? O_B0 : O_B1;
        uint4 pf[16];
        if (c < 15) {
            size_t kr = krb + (size_t)(s0 + 64) * HA;
            size_t vr = vrb + s0 + 64;
            #pragma unroll
            for (int u = 0; u < 4; u++) {
                pf[u]      = *(const uint4*)(&g_kh[kr] + u * 8);
                pf[u + 4]  = *(const uint4*)(&g_kl[kr] + u * 8);
                pf[u + 8]  = *(const uint4*)(&g_vh[vr] + u * 8);
                pf[u + 12] = *(const uint4*)(&g_vl[vr] + u * 8);
            }
        }
        float d[8][4];
        #pragma unroll
        for (int cg = 0; cg < 8; cg++) {
            d[cg][0] = d[cg][1] = d[cg][2] = d[cg][3] = 0.f;
            #pragma unroll
            for (int k = 0; k < 4; k++) {
                u32 off = ((cg * 8 + brow) * 72 + 16 * k + bc8) * 2;
                u32 bh[2], bl[2];
                ldmx2(bh, SB + bb + 0 + off);
                ldmx2(bl, SB + bb + 9216 + off);
                mma16816(d[cg], qhf[k], bh);
                mma16816(d[cg], qhf[k], bl);
                mma16816(d[cg], qlf[k], bh);
            }
            d[cg][0] *= 0.125f; d[cg][1] *= 0.125f;
            d[cg][2] *= 0.125f; d[cg][3] *= 0.125f;
        }
        if (h < 2) {
            float* base = (h == 0 ? g_sc0 : g_sc1);
            #pragma unroll
            for (int cg = 0; cg < 8; cg++) {
                int cc = s0 + cg * 8 + cc0;
                if (r0 < cnt)
                    *(float2*)&base[(size_t)(n0 + r0) * SS + cc] = make_float2(d[cg][0], d[cg][1]);
                if (r0 + 8 < cnt)
                    *(float2*)&base[(size_t)(n0 + r0 + 8) * SS + cc] = make_float2(d[cg][2], d[cg][3]);
            }
        }
        u16 mw[8];
        #pragma unroll
        for (int cg = 0; cg < 8; cg++)
            mw[cg] = *(const u16*)&g_mask[b * SS + s0 + cg * 8 + cc0];
        float cm0 = -FLT_MAX, cm1 = -FLT_MAX;
        #pragma unroll
        for (int cg = 0; cg < 8; cg++) {
            if (mw[cg] & 0xff) { cm0 = fmaxf(cm0, d[cg][0]); cm1 = fmaxf(cm1, d[cg][2]); }
            if (mw[cg] >> 8)   { cm0 = fmaxf(cm0, d[cg][1]); cm1 = fmaxf(cm1, d[cg][3]); }
        }
        cm0 = fmaxf(cm0, __shfl_xor_sync(0xffffffffu, cm0, 1));
        cm0 = fmaxf(cm0, __shfl_xor_sync(0xffffffffu, cm0, 2));
        cm1 = fmaxf(cm1, __shfl_xor_sync(0xffffffffu, cm1, 1));
        cm1 = fmaxf(cm1, __shfl_xor_sync(0xffffffffu, cm1, 2));
        float mn0 = fmaxf(mo0, cm0), mn1 = fmaxf(mo1, cm1);
        float a0 = (mo0 == mn0) ? 1.f : __expf(mo0 - mn0);
        float a1 = (mo1 == mn1) ? 1.f : __expf(mo1 - mn1);
        float cs0 = 0.f, cs1 = 0.f;
        u32 phf[4][4], plf[4][4];
        #pragma unroll
        for (int cg = 0; cg < 8; cg++) {
            float p0 = (mw[cg] & 0xff) ? __expf(d[cg][0] - mn0) : 0.f;
            float p1 = (mw[cg] >> 8)   ? __expf(d[cg][1] - mn0) : 0.f;
            float p2 = (mw[cg] & 0xff) ? __expf(d[cg][2] - mn1) : 0.f;
            float p3 = (mw[cg] >> 8)   ? __expf(d[cg][3] - mn1) : 0.f;
            cs0 += p0 + p1; cs1 += p2 + p3;
            u32 hA = pkbf(p0, p1), hB = pkbf(p2, p3);
            float2 fA = unbf(hA), fB = unbf(hB);
            u32 lA = pkbf(p0 - fA.x, p1 - fA.y), lB = pkbf(p2 - fB.x, p3 - fB.y);
            phf[cg >> 1][(cg & 1) * 2]     = hA;
            phf[cg >> 1][(cg & 1) * 2 + 1] = hB;
            plf[cg >> 1][(cg & 1) * 2]     = lA;
            plf[cg >> 1][(cg & 1) * 2 + 1] = lB;
        }
        ls0 = ls0 * a0 + cs0;  ls1 = ls1 * a1 + cs1;
        mo0 = mn0;  mo1 = mn1;
        #pragma unroll
        for (int cg = 0; cg < 8; cg++) {
            feat[cg][0] *= a0; feat[cg][1] *= a0;
            feat[cg][2] *= a1; feat[cg][3] *= a1;
            #pragma unroll
            for (int k = 0; k < 4; k++) {
                u32 off = ((cg * 8 + brow) * 72 + 16 * k + bc8) * 2;
                u32 bh[2], bl[2];
                ldmx2(bh, SB + bb + 18432 + off);
                ldmx2(bl, SB + bb + 27648 + off);
                mma16816(feat[cg], phf[k], bh);
                mma16816(feat[cg], phf[k], bl);
                mma16816(feat[cg], plf[k], bh);
            }
        }
        if (c < 15) {
            #pragma unroll
            for (int u = 0; u < 4; u++) {
                *(uint4*)(sm8 + bn + 0     + ro + u * 16) = pf[u];
                *(uint4*)(sm8 + bn + 9216  + ro + u * 16) = pf[u + 4];
                *(uint4*)(sm8 + bn + 18432 + ro + u * 16) = pf[u + 8];
                *(uint4*)(sm8 + bn + 27648 + ro + u * 16) = pf[u + 12];
            }
        }
        __syncthreads();
    }

    ls0 += __shfl_xor_sync(0xffffffffu, ls0, 1);
    ls0 += __shfl_xor_sync(0xffffffffu, ls0, 2);
    ls1 += __shfl_xor_sync(0xffffffffu, ls1, 1);
    ls1 += __shfl_xor_sync(0xffffffffu, ls1, 2);
    #pragma unroll
    for (int cg = 0; cg < 8; cg++) {
        *(float2*)&Sc[r0 * 68 + cg * 8 + cc0] = make_float2(feat[cg][0], feat[cg][1]);
        *(float2*)&Sc[(r0 + 8) * 68 + cg * 8 + cc0] = make_float2(feat[cg][2], feat[cg][3]);
    }
    if ((lane & 3) == 0) {
        Al[r0] = 1.f / (ls0 + 1e-9f);
        Al[r0 + 8] = 1.f / (ls1 + 1e-9f);
    }
    __syncthreads();
    if (tid < cnt) {
        float inv = Al[tid];
        const float* gp = &g_gate[(size_t)(n0 + tid) * HA + h * AA];
        size_t fo = (size_t)(n0 + tid) * HA + h * AA;
        const float* sr = &Sc[tid * 68];
        #pragma unroll
        for (int x = 0; x < 16; x++) {
            float4 v = *(const float4*)(sr + x * 4);
            float4 g = *(const float4*)(gp + x * 4);
            float o0 = v.x * inv * g.x, o1 = v.y * inv * g.y;
            float o2 = v.z * inv * g.z, o3 = v.w * inv * g.w;
            u32 h0 = pkbf(o0, o1), h1 = pkbf(o2, o3);
            float2 f0 = unbf(h0), f1 = unbf(h1);
            u32 l0 = pkbf(o0 - f0.x, o1 - f0.y), l1 = pkbf(o2 - f1.x, o3 - f1.y);
            *(uint2*)&g_fh[fo + x * 4] = make_uint2(h0, h1);
            *(uint2*)&g_fl[fo + x * 4] = make_uint2(l0, l1);
        }
    }
}

// ---------------- logits = sc0 + sc1 ---------------------------------------
__global__ void addlog_k(float* __restrict__ logits) {
    size_t i = ((size_t)blockIdx.x * 256 + threadIdx.x) * 4;
    float4 a = *(const float4*)&g_sc0[i];
    float4 b4 = *(const float4*)&g_sc1[i];
    *(float4*)&logits[i] = make_float4(a.x + b4.x, a.y + b4.y, a.z + b4.z, a.w + b4.w);
}

// ---------------- y = sqrt(2)*x + feat @ Wback + bback : double-buffered ---
__global__ void __launch_bounds__(128) back_mma(const float* __restrict__ x,
                                                const float* __restrict__ bback) {
    extern __shared__ __align__(16) unsigned char smd[];
    const u32 SB = s2u(smd);
    int m0 = blockIdx.x * 64, n0 = blockIdx.y * 64;
    int tid = threadIdx.x, lane = tid & 31, w = tid >> 5;
    const int lr = lane & 15;
    const u32 brow = lr & 7, bc8 = (lr >> 3) * 8;
    const int r0 = 16 * w + (lane >> 2), cc0 = (lane & 3) * 2;
    u32 arow = 16 * w + (lane & 7) + ((lane >> 3) & 1) * 8;
    u32 acol = ((lane >> 4) & 1) * 8;
    float acc[8][4];
    #pragma unroll
    for (int cg = 0; cg < 8; cg++)
        acc[cg][0] = acc[cg][1] = acc[cg][2] = acc[cg][3] = 0.f;
    int r = tid >> 1, kh2 = (tid & 1) * 32;
    const u32 ro = (u32)(r * 72 + kh2) * 2;
    size_t fa = (size_t)(m0 + r) * HA + kh2;
    size_t wa = (size_t)(n0 + r) * HA + kh2;
    #pragma unroll
    for (int u = 0; u < 4; u++) {
        *(uint4*)(smd + 0     + ro + u * 16) = *(const uint4*)(&g_fh[fa] + u * 8);
        *(uint4*)(smd + 9216  + ro + u * 16) = *(const uint4*)(&g_fl[fa] + u * 8);
        *(uint4*)(smd + 18432 + ro + u * 16) = *(const uint4*)(&g_wbh[wa] + u * 8);
        *(uint4*)(smd + 27648 + ro + u * 16) = *(const uint4*)(&g_wbl[wa] + u * 8);
    }
    __syncthreads();
    for (int kc = 0; kc < 8; kc++) {
        u32 bb = (kc & 1) ? 36864 : 0, bn = (kc & 1) ? 0 : 36864;
        uint4 pf[16];
        if (kc < 7) {
            int k0 = (kc + 1) * 64;
            #pragma unroll
            for (int u = 0; u < 4; u++) {
                pf[u]      = *(const uint4*)(&g_fh[fa + k0] + u * 8);
                pf[u + 4]  = *(const uint4*)(&g_fl[fa + k0] + u * 8);
                pf[u + 8]  = *(const uint4*)(&g_wbh[wa + k0] + u * 8);
                pf[u + 12] = *(const uint4*)(&g_wbl[wa + k0] + u * 8);
            }
        }
        u32 ahf[4][4], alf[4][4];
        #pragma unroll
        for (int k = 0; k < 4; k++) {
            ldmx4(ahf[k], SB + bb + 0    + (arow * 72 + acol + 16 * k) * 2);
            ldmx4(alf[k], SB + bb + 9216 + (arow * 72 + acol + 16 * k) * 2);
        }
        #pragma unroll
        for (int cg = 0; cg < 8; cg++) {
            #pragma unroll
            for (int k = 0; k < 4; k++) {
                u32 off = ((cg * 8 + brow) * 72 + 16 * k + bc8) * 2;
                u32 bh[2], bl[2];
                ldmx2(bh, SB + bb + 18432 + off);
                ldmx2(bl, SB + bb + 27648 + off);
                mma16816(acc[cg], ahf[k], bh);
                mma16816(acc[cg], ahf[k], bl);
                mma16816(acc[cg], alf[k], bh);
            }
        }
        if (kc < 7) {
            #pragma unroll
            for (int u = 0; u < 4; u++) {
                *(uint4*)(smd + bn + 0     + ro + u * 16) = pf[u];
                *(uint4*)(smd + bn + 9216  + ro + u * 16) = pf[u + 4];
                *(uint4*)(smd + bn + 18432 + ro + u * 16) = pf[u + 8];
                *(uint4*)(smd + bn + 27648 + ro + u * 16) = pf[u + 12];
            }
        }
        __syncthreads();
    }
    const float rt2 = 1.41421356237309515f;
    #pragma unroll
    for (int cg = 0; cg < 8; cg++) {
        int c = n0 + cg * 8 + cc0;
        float b0 = bback[c], b1 = bback[c + 1];
        float2 x0 = *(const float2*)&x[(size_t)(m0 + r0) * IFZ + c];
        float2 x1 = *(const float2*)&x[(size_t)(m0 + r0 + 8) * IFZ + c];
        *(float2*)&g_y[(size_t)(m0 + r0) * IFZ + c] =
            make_float2(rt2 * x0.x + acc[cg][0] + b0, rt2 * x0.y + acc[cg][1] + b1);
        *(float2*)&g_y[(size_t)(m0 + r0 + 8) * IFZ + c] =
            make_float2(rt2 * x1.x + acc[cg][2] + b0, rt2 * x1.y + acc[cg][3] + b1);
    }
}

// ---------------- LayerNorm ------------------------------------------------
__global__ void __launch_bounds__(256) ln_k(const float* __restrict__ gamma,
                                            const float* __restrict__ beta,
                                            float* __restrict__ out) {
    int warp = threadIdx.x >> 5, lane = threadIdx.x & 31;
    int row = blockIdx.x * 8 + warp;
    float4 v0 = *(const float4*)&g_y[(size_t)row * IFZ + lane * 4];
    float4 v1 = *(const float4*)&g_y[(size_t)row * IFZ + 128 + lane * 4];
    float s = v0.x + v0.y + v0.z + v0.w + v1.x + v1.y + v1.z + v1.w;
    #pragma unroll
    for (int d = 16; d; d >>= 1) s += __shfl_xor_sync(0xffffffffu, s, d);
    float mu = s * (1.f / 256.f);
    float q = 0.f;
    q += (v0.x - mu) * (v0.x - mu); q += (v0.y - mu) * (v0.y - mu);
    q += (v0.z - mu) * (v0.z - mu); q += (v0.w - mu) * (v0.w - mu);
    q += (v1.x - mu) * (v1.x - mu); q += (v1.y - mu) * (v1.y - mu);
    q += (v1.z - mu) * (v1.z - mu); q += (v1.w - mu) * (v1.w - mu);
    #pragma unroll
    for (int d = 16; d; d >>= 1) q += __shfl_xor_sync(0xffffffffu, q, d);
    float inv = rsqrtf(q * (1.f / 256.f) + 1e-5f);
    float4 g0 = *(const float4*)&gamma[lane * 4];
    float4 b0 = *(const float4*)&beta[lane * 4];
    float4 g1 = *(const float4*)&gamma[128 + lane * 4];
    float4 b1 = *(const float4*)&beta[128 + lane * 4];
    float4 o0, o1;
    o0.x = (v0.x - mu) * inv * g0.x + b0.x;
    o0.y = (v0.y - mu) * inv * g0.y + b0.y;
    o0.z = (v0.z - mu) * inv * g0.z + b0.z;
    o0.w = (v0.w - mu) * inv * g0.w + b0.w;
    o1.x = (v1.x - mu) * inv * g1.x + b1.x;
    o1.y = (v1.y - mu) * inv * g1.y + b1.y;
    o1.z = (v1.z - mu) * inv * g1.z + b1.z;
    o1.w = (v1.w - mu) * inv * g1.w + b1.w;
    *(float4*)&out[(size_t)row * IFZ + lane * 4] = o0;
    *(float4*)&out[(size_t)row * IFZ + 128 + lane * 4] = o1;
}

// ---------------- launch ---------------------------------------------------
extern "C" void kernel_launch(void* const* d_in, const int* in_sizes, int n_in,
                              void* d_out, int out_size) {
    const float* x     = (const float*)d_in[0];
    const float* emb   = (const float*)d_in[1];
    const void*  mask  = d_in[2];
    const void*  batch = d_in[3];
    const float* Wq    = (const float*)d_in[4];
    const float* Wk    = (const float*)d_in[5];
    const float* Wv    = (const float*)d_in[6];
    const float* Wg    = (const float*)d_in[7];
    const float* bg    = (const float*)d_in[8];
    const float* Wback = (const float*)d_in[9];
    const float* bback = (const float*)d_in[10];
    const float* gamma = (const float*)d_in[11];
    const float* beta  = (const float*)d_in[12];
    float* out    = (float*)d_out;
    float* logits = out + (size_t)NN * IFZ;

    static int smem_set = 0;
    if (!smem_set) {
        cudaFuncSetAttribute(attn_mma, cudaFuncAttributeMaxDynamicSharedMemorySize,
                             ATTN_SMEMB);
        cudaFuncSetAttribute(proj_qg_mma, cudaFuncAttributeMaxDynamicSharedMemorySize,
                             GEMM_SMEMB);
        cudaFuncSetAttribute(proj_kv_mma, cudaFuncAttributeMaxDynamicSharedMemorySize,
                             GEMM_SMEMB);
        cudaFuncSetAttribute(back_mma, cudaFuncAttributeMaxDynamicSharedMemorySize,
                             GEMM_SMEMB);
        smem_set = 1;
    }

    prep_k<<<1, 256>>>(mask, batch);
    conv_ex_k<<<2048, 256>>>(emb, x);
    conv_allw_k<<<dim3(8, 16, 3), 128>>>(Wk, Wv, Wq, Wg, Wback);
    proj_qg_mma<<<dim3(32, 16), 128, GEMM_SMEMB>>>(bg);
    proj_kv_mma<<<dim3(64, 16), 128, GEMM_SMEMB>>>();
    conv_v_k<<<dim3(16, HH, BBATCH), 128>>>();
    attn_mma<<<dim3(MAXT, HH), 128, ATTN_SMEMB>>>();
    addlog_k<<<2048, 256>>>(logits);
    back_mma<<<dim3(32, 4), 128, GEMM_SMEMB>>>(x, bback);
    ln_k<<<256, 256>>>(gamma, beta, out);
}

// round 17
// speedup vs baseline: 1.5391x; 1.5391x over previous
#include <cuda_runtime.h>
#include <cuda_bf16.h>
#include <float.h>
#include <math.h>

#define NN   2048
#define BBATCH 4
#define SS   1024
#define SFZ  384
#define IFZ  256
#define HH   8
#define AA   64
#define HA   512
#define MAXT 36

typedef unsigned long long ull;
typedef unsigned int u32;
typedef unsigned short u16;

__device__ __align__(16) float g_q[NN * HA];
__device__ __align__(16) float g_gate[NN * HA];
__device__ __align__(16) float g_v[BBATCH * SS * HA];
__device__ __align__(16) float g_y[NN * IFZ];
__device__ __align__(16) unsigned char g_mask[BBATCH * SS];
__device__ int g_tb[MAXT], g_ts[MAXT], g_tc[MAXT], g_nt;
__device__ __align__(16) __nv_bfloat16 g_kh[BBATCH * SS * HA];
__device__ __align__(16) __nv_bfloat16 g_kl[BBATCH * SS * HA];
__device__ __align__(16) __nv_bfloat16 g_vh[BBATCH * HH * AA * SS];
__device__ __align__(16) __nv_bfloat16 g_vl[BBATCH * HH * AA * SS];
__device__ __align__(16) float g_sc0[NN * SS];
__device__ __align__(16) float g_sc1[NN * SS];
__device__ __align__(16) __nv_bfloat16 g_eh[BBATCH * SS * SFZ];
__device__ __align__(16) __nv_bfloat16 g_el[BBATCH * SS * SFZ];
__device__ __align__(16) __nv_bfloat16 g_wht[2 * HA * SFZ];
__device__ __align__(16) __nv_bfloat16 g_wlt[2 * HA * SFZ];
__device__ __align__(16) __nv_bfloat16 g_xh[NN * IFZ];
__device__ __align__(16) __nv_bfloat16 g_xl[NN * IFZ];
__device__ __align__(16) __nv_bfloat16 g_qgh[2 * HA * IFZ];
__device__ __align__(16) __nv_bfloat16 g_qgl[2 * HA * IFZ];
__device__ __align__(16) __nv_bfloat16 g_fh[NN * HA];
__device__ __align__(16) __nv_bfloat16 g_fl[NN * HA];
__device__ __align__(16) __nv_bfloat16 g_wbh[IFZ * HA];
__device__ __align__(16) __nv_bfloat16 g_wbl[IFZ * HA];

// ---- bf16 split helpers ----
__device__ __forceinline__ u32 pkbf(float a, float b) {
    __nv_bfloat162 t = __float22bfloat162_rn(make_float2(a, b));
    return *(u32*)&t;
}
__device__ __forceinline__ float2 unbf(u32 h) {
    return __bfloat1622float2(*(__nv_bfloat162*)&h);
}

// ---- ldmatrix + mma.sync ----
static __device__ __forceinline__ u32 s2u(const void* p) {
    u32 a; asm("{.reg .u64 t; cvta.to.shared.u64 t, %1; cvt.u32.u64 %0, t;}" : "=r"(a) : "l"(p));
    return a;
}
__device__ __forceinline__ void ldmx4(u32* r, u32 a) {
    asm volatile("ldmatrix.sync.aligned.m8n8.x4.shared.b16 {%0,%1,%2,%3},[%4];"
                 : "=r"(r[0]), "=r"(r[1]), "=r"(r[2]), "=r"(r[3]) : "r"(a));
}
__device__ __forceinline__ void ldmx2(u32* r, u32 a) {
    asm volatile("ldmatrix.sync.aligned.m8n8.x2.shared.b16 {%0,%1},[%2];"
                 : "=r"(r[0]), "=r"(r[1]) : "r"(a));
}
__device__ __forceinline__ void mma16816(float* d, const u32* a, const u32* bb) {
    asm volatile("mma.sync.aligned.m16n8k16.row.col.f32.bf16.bf16.f32 "
                 "{%0,%1,%2,%3},{%4,%5,%6,%7},{%8,%9},{%0,%1,%2,%3};"
                 : "+f"(d[0]), "+f"(d[1]), "+f"(d[2]), "+f"(d[3])
                 : "r"(a[0]), "r"(a[1]), "r"(a[2]), "r"(a[3]), "r"(bb[0]), "r"(bb[1]));
}

// attn smem layout
#define O_QH 0
#define O_QL 9216
#define O_SC 0
#define O_AL 17408
#define O_B0 18432
#define O_B1 55296
#define ATTN_SMEMB 92160

// ---------------- prep ------------------------------------------------------
__global__ void prep_k(const void* mask_in, const void* batch_in) {
    __shared__ int flg[2];
    __shared__ int cnt[BBATCH];
    int tid = threadIdx.x;
    if (tid < 2) flg[tid] = 0;
    if (tid < BBATCH) cnt[tid] = 0;
    __syncthreads();
    const unsigned int* bw = (const unsigned int*)batch_in;
    unsigned int o = 0;
    for (int i = tid * 2 + 1; i < NN; i += blockDim.x * 2) o |= bw[i];
    if (o) atomicOr(&flg[0], 1);
    const unsigned char* mb = (const unsigned char*)mask_in;
    int f = 0;
    for (int i = tid; i < BBATCH * SS; i += blockDim.x)
        if ((i & 3) && mb[i]) f = 1;
    if (f) atomicOr(&flg[1], 1);
    __syncthreads();
    int is32 = flg[0], isb = flg[1];
    int lc[BBATCH] = {0, 0, 0, 0};
    for (int i = tid; i < NN; i += blockDim.x) {
        int v = is32 ? ((const int*)batch_in)[i]
                     : (int)((const long long*)batch_in)[i];
        lc[v & 3]++;
    }
    #pragma unroll
    for (int b = 0; b < BBATCH; b++) if (lc[b]) atomicAdd(&cnt[b], lc[b]);
    for (int i = tid; i < BBATCH * SS; i += blockDim.x)
        g_mask[i] = isb ? (mb[i] ? 1 : 0) : (((const int*)mask_in)[i] ? 1 : 0);
    __syncthreads();
    if (tid == 0) {
        int st = 0, t = 0;
        for (int b = 0; b < BBATCH; b++) {
            int e = st + cnt[b];
            for (int s = st; s < e; s += 64) {
                g_tb[t] = b; g_ts[t] = s; g_tc[t] = min(64, e - s); t++;
            }
            st = e;
        }
        g_nt = t;
    }
}

// ---------------- emb + x -> bf16 hi/lo (merged) ---------------------------
__global__ void conv_ex_k(const float* __restrict__ emb, const float* __restrict__ x) {
    int bid = blockIdx.x;
    const float* src;
    __nv_bfloat16 *oh, *ol;
    size_t i;
    if (bid < 1536) {
        src = emb; oh = g_eh; ol = g_el;
        i = ((size_t)bid * 256 + threadIdx.x) * 4;
    } else {
        src = x; oh = g_xh; ol = g_xl;
        i = ((size_t)(bid - 1536) * 256 + threadIdx.x) * 4;
    }
    float4 v = *(const float4*)&src[i];
    u32 h0 = pkbf(v.x, v.y), h1 = pkbf(v.z, v.w);
    float2 f0 = unbf(h0), f1 = unbf(h1);
    u32 l0 = pkbf(v.x - f0.x, v.y - f0.y), l1 = pkbf(v.z - f1.x, v.w - f1.y);
    *(uint2*)&oh[i] = make_uint2(h0, h1);
    *(uint2*)&ol[i] = make_uint2(l0, l1);
}

// ---------------- all weight transposers (merged) --------------------------
__global__ void __launch_bounds__(128) conv_allw_k(const float* __restrict__ Wk,
                                                   const float* __restrict__ Wv,
                                                   const float* __restrict__ Wq,
                                                   const float* __restrict__ Wg,
                                                   const float* __restrict__ Wb) {
    __shared__ float buf[64 * 68];
    int z = blockIdx.z;
    int ktiles = (z == 0) ? 6 : (z == 1) ? 4 : 8;
    int ntiles = (z == 2) ? 4 : 16;
    if ((int)blockIdx.x >= ktiles || (int)blockIdx.y >= ntiles) return;
    int kc = blockIdx.x * 64, ng = blockIdx.y * 64;
    const float* W; int srcS, outS, nb;
    __nv_bfloat16 *oh, *ol;
    if (z == 0) { W = (ng < HA) ? Wk : Wv; nb = ng & (HA - 1); srcS = HA; outS = SFZ; oh = g_wht; ol = g_wlt; }
    else if (z == 1) { W = (ng < HA) ? Wq : Wg; nb = ng & (HA - 1); srcS = HA; outS = IFZ; oh = g_qgh; ol = g_qgl; }
    else { W = Wb; nb = ng; srcS = IFZ; outS = HA; oh = g_wbh; ol = g_wbl; }
    int tid = threadIdx.x;
    #pragma unroll
    for (int p = 0; p < 8; p++) {
        int idx = tid + p * 128, kk = idx >> 4, nn = (idx & 15) * 4;
        *(float4*)&buf[kk * 68 + nn] =
            *(const float4*)&W[(size_t)(kc + kk) * srcS + nb + nn];
    }
    __syncthreads();
    int nn = tid >> 1, kh = (tid & 1) * 32;
    u32 hv[16], lv[16];
    #pragma unroll
    for (int p = 0; p < 16; p++) {
        float x0 = buf[(kh + 2 * p) * 68 + nn], x1 = buf[(kh + 2 * p + 1) * 68 + nn];
        hv[p] = pkbf(x0, x1);
        float2 f = unbf(hv[p]);
        lv[p] = pkbf(x0 - f.x, x1 - f.y);
    }
    size_t o = (size_t)(ng + nn) * outS + kc + kh;
    #pragma unroll
    for (int p = 0; p < 4; p++) {
        *(uint4*)&oh[o + p * 8] = make_uint4(hv[4*p], hv[4*p+1], hv[4*p+2], hv[4*p+3]);
        *(uint4*)&ol[o + p * 8] = make_uint4(lv[4*p], lv[4*p+1], lv[4*p+2], lv[4*p+3]);
    }
}

// ---------------- q,gate = x @ Wq/Wg : mma.sync bf16 3-term (single-buf) ---
__global__ void __launch_bounds__(128) proj_qg_mma(const float* __restrict__ bg) {
    __shared__ __align__(16) unsigned char sm[36864];
    const u32 SB = s2u(sm);
    int m0 = blockIdx.x * 64, ng = blockIdx.y * 64;
    int tid = threadIdx.x, lane = tid & 31, w = tid >> 5;
    const int lr = lane & 15;
    const u32 brow = lr & 7, bc8 = (lr >> 3) * 8;
    const int r0 = 16 * w + (lane >> 2), cc0 = (lane & 3) * 2;
    u32 arow = 16 * w + (lane & 7) + ((lane >> 3) & 1) * 8;
    u32 acol = ((lane >> 4) & 1) * 8;
    float acc[8][4];
    #pragma unroll
    for (int cg = 0; cg < 8; cg++)
        acc[cg][0] = acc[cg][1] = acc[cg][2] = acc[cg][3] = 0.f;
    int r = tid >> 1, kh2 = (tid & 1) * 32;
    for (int kc = 0; kc < 4; kc++) {
        int k0 = kc * 64;
        {
            size_t xa = (size_t)(m0 + r) * IFZ + k0 + kh2;
            size_t wa = (size_t)(ng + r) * IFZ + k0 + kh2;
            u32 ro = (u32)(r * 72 + kh2) * 2;
            #pragma unroll
            for (int u = 0; u < 4; u++) {
                *(uint4*)(sm + 0     + ro + u * 16) = *(const uint4*)(&g_xh[xa] + u * 8);
                *(uint4*)(sm + 9216  + ro + u * 16) = *(const uint4*)(&g_xl[xa] + u * 8);
                *(uint4*)(sm + 18432 + ro + u * 16) = *(const uint4*)(&g_qgh[wa] + u * 8);
                *(uint4*)(sm + 27648 + ro + u * 16) = *(const uint4*)(&g_qgl[wa] + u * 8);
            }
        }
        __syncthreads();
        u32 ahf[4][4], alf[4][4];
        #pragma unroll
        for (int k = 0; k < 4; k++) {
            ldmx4(ahf[k], SB + 0    + (arow * 72 + acol + 16 * k) * 2);
            ldmx4(alf[k], SB + 9216 + (arow * 72 + acol + 16 * k) * 2);
        }
        #pragma unroll
        for (int cg = 0; cg < 8; cg++) {
            #pragma unroll
            for (int k = 0; k < 4; k++) {
                u32 off = ((cg * 8 + brow) * 72 + 16 * k + bc8) * 2;
                u32 bh[2], bl[2];
                ldmx2(bh, SB + 18432 + off);
                ldmx2(bl, SB + 27648 + off);
                mma16816(acc[cg], ahf[k], bh);
                mma16816(acc[cg], ahf[k], bl);
                mma16816(acc[cg], alf[k], bh);
            }
        }
        __syncthreads();
    }
    bool isg = (ng >= HA);
    int nc0 = ng & (HA - 1);
    if (isg) {
        #pragma unroll
        for (int cg = 0; cg < 8; cg++) {
            int c = nc0 + cg * 8 + cc0;
            float b0 = bg[c], b1 = bg[c + 1];
            float2 o0, o1;
            o0.x = 1.0f / (1.0f + __expf(-(acc[cg][0] + b0)));
            o0.y = 1.0f / (1.0f + __expf(-(acc[cg][1] + b1)));
            o1.x = 1.0f / (1.0f + __expf(-(acc[cg][2] + b0)));
            o1.y = 1.0f / (1.0f + __expf(-(acc[cg][3] + b1)));
            *(float2*)&g_gate[(size_t)(m0 + r0) * HA + c] = o0;
            *(float2*)&g_gate[(size_t)(m0 + r0 + 8) * HA + c] = o1;
        }
    } else {
        #pragma unroll
        for (int cg = 0; cg < 8; cg++) {
            int c = nc0 + cg * 8 + cc0;
            *(float2*)&g_q[(size_t)(m0 + r0) * HA + c] = make_float2(acc[cg][0], acc[cg][1]);
            *(float2*)&g_q[(size_t)(m0 + r0 + 8) * HA + c] = make_float2(acc[cg][2], acc[cg][3]);
        }
    }
}

// ---------------- k,v = emb @ Wk/Wv : mma.sync (single-buf, K fused) -------
__global__ void __launch_bounds__(128) proj_kv_mma() {
    __shared__ __align__(16) unsigned char sm[36864];
    const u32 SB = s2u(sm);
    int m0 = blockIdx.x * 64, ng = blockIdx.y * 64;
    int tid = threadIdx.x, lane = tid & 31, w = tid >> 5;
    const int lr = lane & 15;
    const u32 brow = lr & 7, bc8 = (lr >> 3) * 8;
    const int r0 = 16 * w + (lane >> 2), cc0 = (lane & 3) * 2;
    u32 arow = 16 * w + (lane & 7) + ((lane >> 3) & 1) * 8;
    u32 acol = ((lane >> 4) & 1) * 8;
    float acc[8][4];
    #pragma unroll
    for (int cg = 0; cg < 8; cg++)
        acc[cg][0] = acc[cg][1] = acc[cg][2] = acc[cg][3] = 0.f;
    int r = tid >> 1, kh2 = (tid & 1) * 32;
    for (int kc = 0; kc < 6; kc++) {
        int k0 = kc * 64;
        {
            size_t ea = (size_t)(m0 + r) * SFZ + k0 + kh2;
            size_t wa = (size_t)(ng + r) * SFZ + k0 + kh2;
            u32 ro = (u32)(r * 72 + kh2) * 2;
            #pragma unroll
            for (int u = 0; u < 4; u++) {
                *(uint4*)(sm + 0     + ro + u * 16) = *(const uint4*)(&g_eh[ea] + u * 8);
                *(uint4*)(sm + 9216  + ro + u * 16) = *(const uint4*)(&g_el[ea] + u * 8);
                *(uint4*)(sm + 18432 + ro + u * 16) = *(const uint4*)(&g_wht[wa] + u * 8);
                *(uint4*)(sm + 27648 + ro + u * 16) = *(const uint4*)(&g_wlt[wa] + u * 8);
            }
        }
        __syncthreads();
        u32 ahf[4][4], alf[4][4];
        #pragma unroll
        for (int k = 0; k < 4; k++) {
            ldmx4(ahf[k], SB + 0    + (arow * 72 + acol + 16 * k) * 2);
            ldmx4(alf[k], SB + 9216 + (arow * 72 + acol + 16 * k) * 2);
        }
        #pragma unroll
        for (int cg = 0; cg < 8; cg++) {
            #pragma unroll
            for (int k = 0; k < 4; k++) {
                u32 off = ((cg * 8 + brow) * 72 + 16 * k + bc8) * 2;
                u32 bh[2], bl[2];
                ldmx2(bh, SB + 18432 + off);
                ldmx2(bl, SB + 27648 + off);
                mma16816(acc[cg], ahf[k], bh);
                mma16816(acc[cg], ahf[k], bl);
                mma16816(acc[cg], alf[k], bh);
            }
        }
        __syncthreads();
    }
    bool isv = (ng >= HA);
    int nc0 = ng & (HA - 1);
    if (isv) {
        #pragma unroll
        for (int cg = 0; cg < 8; cg++) {
            int c = nc0 + cg * 8 + cc0;
            *(float2*)&g_v[(size_t)(m0 + r0) * HA + c] = make_float2(acc[cg][0], acc[cg][1]);
            *(float2*)&g_v[(size_t)(m0 + r0 + 8) * HA + c] = make_float2(acc[cg][2], acc[cg][3]);
        }
    } else {
        #pragma unroll
        for (int cg = 0; cg < 8; cg++) {
            int c = nc0 + cg * 8 + cc0;
            u32 h0 = pkbf(acc[cg][0], acc[cg][1]);
            u32 h1 = pkbf(acc[cg][2], acc[cg][3]);
            float2 f0 = unbf(h0), f1 = unbf(h1);
            u32 l0 = pkbf(acc[cg][0] - f0.x, acc[cg][1] - f0.y);
            u32 l1 = pkbf(acc[cg][2] - f1.x, acc[cg][3] - f1.y);
            *(u32*)&g_kh[(size_t)(m0 + r0) * HA + c] = h0;
            *(u32*)&g_kl[(size_t)(m0 + r0) * HA + c] = l0;
            *(u32*)&g_kh[(size_t)(m0 + r0 + 8) * HA + c] = h1;
            *(u32*)&g_kl[(size_t)(m0 + r0 + 8) * HA + c] = l1;
        }
    }
}

// ---------------- V -> transposed [b][h][a][s] bf16 hi/lo ------------------
__global__ void __launch_bounds__(128) conv_v_k() {
    __shared__ float buf[64 * 68];
    int b = blockIdx.z, h = blockIdx.y, s0 = blockIdx.x * 64;
    int tid = threadIdx.x;
    #pragma unroll
    for (int p = 0; p < 8; p++) {
        int idx = tid + p * 128, s = idx >> 4, q = idx & 15;
        *(float4*)&buf[s * 68 + q * 4] =
            *(const float4*)&g_v[((size_t)(b << 10) + s0 + s) * HA + h * AA + q * 4];
    }
    __syncthreads();
    int aa = tid >> 1, sh = (tid & 1) * 32;
    u32 hv[16], lv[16];
    #pragma unroll
    for (int p = 0; p < 16; p++) {
        float x0 = buf[(sh + 2 * p) * 68 + aa], x1 = buf[(sh + 2 * p + 1) * 68 + aa];
        hv[p] = pkbf(x0, x1);
        float2 f = unbf(hv[p]);
        lv[p] = pkbf(x0 - f.x, x1 - f.y);
    }
    size_t o = ((size_t)(b * HH + h) * AA + aa) * SS + s0 + sh;
    #pragma unroll
    for (int p = 0; p < 4; p++) {
        *(uint4*)&g_vh[o + p * 8] = make_uint4(hv[4*p], hv[4*p+1], hv[4*p+2], hv[4*p+3]);
        *(uint4*)&g_vl[o + p * 8] = make_uint4(lv[4*p], lv[4*p+1], lv[4*p+2], lv[4*p+3]);
    }
}

// ---------------- attention: reg-resident flash + double-buffered staging --
__global__ void __launch_bounds__(128) attn_mma() {
    extern __shared__ unsigned char sm8[];
    const int t = blockIdx.x;
    if (t >= g_nt) return;
    const int h = blockIdx.y;
    const int b = g_tb[t], n0 = g_ts[t], cnt = g_tc[t];
    const int tid = threadIdx.x, lane = tid & 31, w = tid >> 5;
    const u32 SB = s2u(sm8);
    float* Sc = (float*)(sm8 + O_SC);
    float* Al = (float*)(sm8 + O_AL);
    const int jr = tid >> 1, half = (tid & 1) * 32;
    const u32 ro = (u32)(jr * 72 + half) * 2;
    const size_t krb = ((size_t)(b << 10) + jr) * HA + h * AA + half;
    const size_t vrb = ((size_t)(b * HH + h) * AA + jr) * SS + half;

    {
        bool val = jr < cnt;
        const float* q = &g_q[(size_t)(n0 + jr) * HA + h * AA + half];
        #pragma unroll
        for (int u = 0; u < 4; u++) {
            float4 x0 = val ? *(const float4*)(q + u * 8) : make_float4(0, 0, 0, 0);
            float4 x1 = val ? *(const float4*)(q + u * 8 + 4) : make_float4(0, 0, 0, 0);
            u32 h0 = pkbf(x0.x, x0.y), h1 = pkbf(x0.z, x0.w);
            u32 h2 = pkbf(x1.x, x1.y), h3 = pkbf(x1.z, x1.w);
            float2 f0 = unbf(h0), f1 = unbf(h1), f2 = unbf(h2), f3 = unbf(h3);
            u32 l0 = pkbf(x0.x - f0.x, x0.y - f0.y), l1 = pkbf(x0.z - f1.x, x0.w - f1.y);
            u32 l2 = pkbf(x1.x - f2.x, x1.y - f2.y), l3 = pkbf(x1.z - f3.x, x1.w - f3.y);
            *(uint4*)(sm8 + O_QH + ro + u * 16) = make_uint4(h0, h1, h2, h3);
            *(uint4*)(sm8 + O_QL + ro + u * 16) = make_uint4(l0, l1, l2, l3);
        }
    }
    __syncthreads();
    u32 qhf[4][4], qlf[4][4];
    {
        u32 arow = 16 * w + (lane & 7) + ((lane >> 3) & 1) * 8;
        u32 acol = ((lane >> 4) & 1) * 8;
        #pragma unroll
        for (int k = 0; k < 4; k++) {
            ldmx4(qhf[k], SB + O_QH + (arow * 72 + acol + 16 * k) * 2);
            ldmx4(qlf[k], SB + O_QL + (arow * 72 + acol + 16 * k) * 2);
        }
    }
    __syncthreads();

    #pragma unroll
    for (int u = 0; u < 4; u++) {
        *(uint4*)(sm8 + O_B0 + 0     + ro + u * 16) = *(const uint4*)(&g_kh[krb] + u * 8);
        *(uint4*)(sm8 + O_B0 + 9216  + ro + u * 16) = *(const uint4*)(&g_kl[krb] + u * 8);
        *(uint4*)(sm8 + O_B0 + 18432 + ro + u * 16) = *(const uint4*)(&g_vh[vrb] + u * 8);
        *(uint4*)(sm8 + O_B0 + 27648 + ro + u * 16) = *(const uint4*)(&g_vl[vrb] + u * 8);
    }
    __syncthreads();

    const int lr = lane & 15;
    const u32 brow = lr & 7, bc8 = (lr >> 3) * 8;
    const int r0 = 16 * w + (lane >> 2), cc0 = (lane & 3) * 2;
    float mo0 = -FLT_MAX, mo1 = -FLT_MAX, ls0 = 0.f, ls1 = 0.f;
    float feat[8][4];
    #pragma unroll
    for (int cg = 0; cg < 8; cg++)
        feat[cg][0] = feat[cg][1] = feat[cg][2] = feat[cg][3] = 0.f;

    for (int c = 0; c < 16; c++) {
        int s0 = c * 64;
        u32 bb = (c & 1) ? O_B1 : O_B0;
        u32 bn = (c & 1) ? O_B0 : O_B1;
        uint4 pf[16];
        if (c < 15) {
            size_t kr = krb + (size_t)(s0 + 64) * HA;
            size_t vr = vrb + s0 + 64;
            #pragma unroll
            for (int u = 0; u < 4; u++) {
                pf[u]      = *(const uint4*)(&g_kh[kr] + u * 8);
                pf[u + 4]  = *(const uint4*)(&g_kl[kr] + u * 8);
                pf[u + 8]  = *(const uint4*)(&g_vh[vr] + u * 8);
                pf[u + 12] = *(const uint4*)(&g_vl[vr] + u * 8);
            }
        }
        float d[8][4];
        #pragma unroll
        for (int cg = 0; cg < 8; cg++) {
            d[cg][0] = d[cg][1] = d[cg][2] = d[cg][3] = 0.f;
            #pragma unroll
            for (int k = 0; k < 4; k++) {
                u32 off = ((cg * 8 + brow) * 72 + 16 * k + bc8) * 2;
                u32 bh[2], bl[2];
                ldmx2(bh, SB + bb + 0 + off);
                ldmx2(bl, SB + bb + 9216 + off);
                mma16816(d[cg], qhf[k], bh);
                mma16816(d[cg], qhf[k], bl);
                mma16816(d[cg], qlf[k], bh);
            }
            d[cg][0] *= 0.125f; d[cg][1] *= 0.125f;
            d[cg][2] *= 0.125f; d[cg][3] *= 0.125f;
        }
        if (h < 2) {
            float* base = (h == 0 ? g_sc0 : g_sc1);
            #pragma unroll
            for (int cg = 0; cg < 8; cg++) {
                int cc = s0 + cg * 8 + cc0;
                if (r0 < cnt)
                    *(float2*)&base[(size_t)(n0 + r0) * SS + cc] = make_float2(d[cg][0], d[cg][1]);
                if (r0 + 8 < cnt)
                    *(float2*)&base[(size_t)(n0 + r0 + 8) * SS + cc] = make_float2(d[cg][2], d[cg][3]);
            }
        }
        u16 mw[8];
        #pragma unroll
        for (int cg = 0; cg < 8; cg++)
            mw[cg] = *(const u16*)&g_mask[b * SS + s0 + cg * 8 + cc0];
        float cm0 = -FLT_MAX, cm1 = -FLT_MAX;
        #pragma unroll
        for (int cg = 0; cg < 8; cg++) {
            if (mw[cg] & 0xff) { cm0 = fmaxf(cm0, d[cg][0]); cm1 = fmaxf(cm1, d[cg][2]); }
            if (mw[cg] >> 8)   { cm0 = fmaxf(cm0, d[cg][1]); cm1 = fmaxf(cm1, d[cg][3]); }
        }
        cm0 = fmaxf(cm0, __shfl_xor_sync(0xffffffffu, cm0, 1));
        cm0 = fmaxf(cm0, __shfl_xor_sync(0xffffffffu, cm0, 2));
        cm1 = fmaxf(cm1, __shfl_xor_sync(0xffffffffu, cm1, 1));
        cm1 = fmaxf(cm1, __shfl_xor_sync(0xffffffffu, cm1, 2));
        float mn0 = fmaxf(mo0, cm0), mn1 = fmaxf(mo1, cm1);
        float a0 = (mo0 == mn0) ? 1.f : __expf(mo0 - mn0);
        float a1 = (mo1 == mn1) ? 1.f : __expf(mo1 - mn1);
        float cs0 = 0.f, cs1 = 0.f;
        u32 phf[4][4], plf[4][4];
        #pragma unroll
        for (int cg = 0; cg < 8; cg++) {
            float p0 = (mw[cg] & 0xff) ? __expf(d[cg][0] - mn0) : 0.f;
            float p1 = (mw[cg] >> 8)   ? __expf(d[cg][1] - mn0) : 0.f;
            float p2 = (mw[cg] & 0xff) ? __expf(d[cg][2] - mn1) : 0.f;
            float p3 = (mw[cg] >> 8)   ? __expf(d[cg][3] - mn1) : 0.f;
            cs0 += p0 + p1; cs1 += p2 + p3;
            u32 hA = pkbf(p0, p1), hB = pkbf(p2, p3);
            float2 fA = unbf(hA), fB = unbf(hB);
            u32 lA = pkbf(p0 - fA.x, p1 - fA.y), lB = pkbf(p2 - fB.x, p3 - fB.y);
            phf[cg >> 1][(cg & 1) * 2]     = hA;
            phf[cg >> 1][(cg & 1) * 2 + 1] = hB;
            plf[cg >> 1][(cg & 1) * 2]     = lA;
            plf[cg >> 1][(cg & 1) * 2 + 1] = lB;
        }
        ls0 = ls0 * a0 + cs0;  ls1 = ls1 * a1 + cs1;
        mo0 = mn0;  mo1 = mn1;
        #pragma unroll
        for (int cg = 0; cg < 8; cg++) {
            feat[cg][0] *= a0; feat[cg][1] *= a0;
            feat[cg][2] *= a1; feat[cg][3] *= a1;
            #pragma unroll
            for (int k = 0; k < 4; k++) {
                u32 off = ((cg * 8 + brow) * 72 + 16 * k + bc8) * 2;
                u32 bh[2], bl[2];
                ldmx2(bh, SB + bb + 18432 + off);
                ldmx2(bl, SB + bb + 27648 + off);
                mma16816(feat[cg], phf[k], bh);
                mma16816(feat[cg], phf[k], bl);
                mma16816(feat[cg], plf[k], bh);
            }
        }
        if (c < 15) {
            #pragma unroll
            for (int u = 0; u < 4; u++) {
                *(uint4*)(sm8 + bn + 0     + ro + u * 16) = pf[u];
                *(uint4*)(sm8 + bn + 9216  + ro + u * 16) = pf[u + 4];
                *(uint4*)(sm8 + bn + 18432 + ro + u * 16) = pf[u + 8];
                *(uint4*)(sm8 + bn + 27648 + ro + u * 16) = pf[u + 12];
            }
        }
        __syncthreads();
    }

    ls0 += __shfl_xor_sync(0xffffffffu, ls0, 1);
    ls0 += __shfl_xor_sync(0xffffffffu, ls0, 2);
    ls1 += __shfl_xor_sync(0xffffffffu, ls1, 1);
    ls1 += __shfl_xor_sync(0xffffffffu, ls1, 2);
    #pragma unroll
    for (int cg = 0; cg < 8; cg++) {
        *(float2*)&Sc[r0 * 68 + cg * 8 + cc0] = make_float2(feat[cg][0], feat[cg][1]);
        *(float2*)&Sc[(r0 + 8) * 68 + cg * 8 + cc0] = make_float2(feat[cg][2], feat[cg][3]);
    }
    if ((lane & 3) == 0) {
        Al[r0] = 1.f / (ls0 + 1e-9f);
        Al[r0 + 8] = 1.f / (ls1 + 1e-9f);
    }
    __syncthreads();
    if (tid < cnt) {
        float inv = Al[tid];
        const float* gp = &g_gate[(size_t)(n0 + tid) * HA + h * AA];
        size_t fo = (size_t)(n0 + tid) * HA + h * AA;
        const float* sr = &Sc[tid * 68];
        #pragma unroll
        for (int x = 0; x < 16; x++) {
            float4 v = *(const float4*)(sr + x * 4);
            float4 g = *(const float4*)(gp + x * 4);
            float o0 = v.x * inv * g.x, o1 = v.y * inv * g.y;
            float o2 = v.z * inv * g.z, o3 = v.w * inv * g.w;
            u32 h0 = pkbf(o0, o1), h1 = pkbf(o2, o3);
            float2 f0 = unbf(h0), f1 = unbf(h1);
            u32 l0 = pkbf(o0 - f0.x, o1 - f0.y), l1 = pkbf(o2 - f1.x, o3 - f1.y);
            *(uint2*)&g_fh[fo + x * 4] = make_uint2(h0, h1);
            *(uint2*)&g_fl[fo + x * 4] = make_uint2(l0, l1);
        }
    }
}

// ---------------- logits = sc0 + sc1 ---------------------------------------
__global__ void addlog_k(float* __restrict__ logits) {
    size_t i = ((size_t)blockIdx.x * 256 + threadIdx.x) * 4;
    float4 a = *(const float4*)&g_sc0[i];
    float4 b4 = *(const float4*)&g_sc1[i];
    *(float4*)&logits[i] = make_float4(a.x + b4.x, a.y + b4.y, a.z + b4.z, a.w + b4.w);
}

// ---------------- y = sqrt(2)*x + feat @ Wback + bback : mma (single-buf) --
__global__ void __launch_bounds__(128) back_mma(const float* __restrict__ x,
                                                const float* __restrict__ bback) {
    __shared__ __align__(16) unsigned char sm[36864];
    const u32 SB = s2u(sm);
    int m0 = blockIdx.x * 64, n0 = blockIdx.y * 64;
    int tid = threadIdx.x, lane = tid & 31, w = tid >> 5;
    const int lr = lane & 15;
    const u32 brow = lr & 7, bc8 = (lr >> 3) * 8;
    const int r0 = 16 * w + (lane >> 2), cc0 = (lane & 3) * 2;
    u32 arow = 16 * w + (lane & 7) + ((lane >> 3) & 1) * 8;
    u32 acol = ((lane >> 4) & 1) * 8;
    float acc[8][4];
    #pragma unroll
    for (int cg = 0; cg < 8; cg++)
        acc[cg][0] = acc[cg][1] = acc[cg][2] = acc[cg][3] = 0.f;
    int r = tid >> 1, kh2 = (tid & 1) * 32;
    for (int kc = 0; kc < 8; kc++) {
        int k0 = kc * 64;
        {
            size_t fa = (size_t)(m0 + r) * HA + k0 + kh2;
            size_t wa = (size_t)(n0 + r) * HA + k0 + kh2;
            u32 ro = (u32)(r * 72 + kh2) * 2;
            #pragma unroll
            for (int u = 0; u < 4; u++) {
                *(uint4*)(sm + 0     + ro + u * 16) = *(const uint4*)(&g_fh[fa] + u * 8);
                *(uint4*)(sm + 9216  + ro + u * 16) = *(const uint4*)(&g_fl[fa] + u * 8);
                *(uint4*)(sm + 18432 + ro + u * 16) = *(const uint4*)(&g_wbh[wa] + u * 8);
                *(uint4*)(sm + 27648 + ro + u * 16) = *(const uint4*)(&g_wbl[wa] + u * 8);
            }
        }
        __syncthreads();
        u32 ahf[4][4], alf[4][4];
        #pragma unroll
        for (int k = 0; k < 4; k++) {
            ldmx4(ahf[k], SB + 0    + (arow * 72 + acol + 16 * k) * 2);
            ldmx4(alf[k], SB + 9216 + (arow * 72 + acol + 16 * k) * 2);
        }
        #pragma unroll
        for (int cg = 0; cg < 8; cg++) {
            #pragma unroll
            for (int k = 0; k < 4; k++) {
                u32 off = ((cg * 8 + brow) * 72 + 16 * k + bc8) * 2;
                u32 bh[2], bl[2];
                ldmx2(bh, SB + 18432 + off);
                ldmx2(bl, SB + 27648 + off);
                mma16816(acc[cg], ahf[k], bh);
                mma16816(acc[cg], ahf[k], bl);
                mma16816(acc[cg], alf[k], bh);
            }
        }
        __syncthreads();
    }
    const float rt2 = 1.41421356237309515f;
    #pragma unroll
    for (int cg = 0; cg < 8; cg++) {
        int c = n0 + cg * 8 + cc0;
        float b0 = bback[c], b1 = bback[c + 1];
        float2 x0 = *(const float2*)&x[(size_t)(m0 + r0) * IFZ + c];
        float2 x1 = *(const float2*)&x[(size_t)(m0 + r0 + 8) * IFZ + c];
        *(float2*)&g_y[(size_t)(m0 + r0) * IFZ + c] =
            make_float2(rt2 * x0.x + acc[cg][0] + b0, rt2 * x0.y + acc[cg][1] + b1);
        *(float2*)&g_y[(size_t)(m0 + r0 + 8) * IFZ + c] =
            make_float2(rt2 * x1.x + acc[cg][2] + b0, rt2 * x1.y + acc[cg][3] + b1);
    }
}

// ---------------- LayerNorm ------------------------------------------------
__global__ void __launch_bounds__(256) ln_k(const float* __restrict__ gamma,
                                            const float* __restrict__ beta,
                                            float* __restrict__ out) {
    int warp = threadIdx.x >> 5, lane = threadIdx.x & 31;
    int row = blockIdx.x * 8 + warp;
    float4 v0 = *(const float4*)&g_y[(size_t)row * IFZ + lane * 4];
    float4 v1 = *(const float4*)&g_y[(size_t)row * IFZ + 128 + lane * 4];
    float s = v0.x + v0.y + v0.z + v0.w + v1.x + v1.y + v1.z + v1.w;
    #pragma unroll
    for (int d = 16; d; d >>= 1) s += __shfl_xor_sync(0xffffffffu, s, d);
    float mu = s * (1.f / 256.f);
    float q = 0.f;
    q += (v0.x - mu) * (v0.x - mu); q += (v0.y - mu) * (v0.y - mu);
    q += (v0.z - mu) * (v0.z - mu); q += (v0.w - mu) * (v0.w - mu);
    q += (v1.x - mu) * (v1.x - mu); q += (v1.y - mu) * (v1.y - mu);
    q += (v1.z - mu) * (v1.z - mu); q += (v1.w - mu) * (v1.w - mu);
    #pragma unroll
    for (int d = 16; d; d >>= 1) q += __shfl_xor_sync(0xffffffffu, q, d);
    float inv = rsqrtf(q * (1.f / 256.f) + 1e-5f);
    float4 g0 = *(const float4*)&gamma[lane * 4];
    float4 b0 = *(const float4*)&beta[lane * 4];
    float4 g1 = *(const float4*)&gamma[128 + lane * 4];
    float4 b1 = *(const float4*)&beta[128 + lane * 4];
    float4 o0, o1;
    o0.x = (v0.x - mu) * inv * g0.x + b0.x;
    o0.y = (v0.y - mu) * inv * g0.y + b0.y;
    o0.z = (v0.z - mu) * inv * g0.z + b0.z;
    o0.w = (v0.w - mu) * inv * g0.w + b0.w;
    o1.x = (v1.x - mu) * inv * g1.x + b1.x;
    o1.y = (v1.y - mu) * inv * g1.y + b1.y;
    o1.z = (v1.z - mu) * inv * g1.z + b1.z;
    o1.w = (v1.w - mu) * inv * g1.w + b1.w;
    *(float4*)&out[(size_t)row * IFZ + lane * 4] = o0;
    *(float4*)&out[(size_t)row * IFZ + 128 + lane * 4] = o1;
}

// ---------------- launch ---------------------------------------------------
extern "C" void kernel_launch(void* const* d_in, const int* in_sizes, int n_in,
                              void* d_out, int out_size) {
    const float* x     = (const float*)d_in[0];
    const float* emb   = (const float*)d_in[1];
    const void*  mask  = d_in[2];
    const void*  batch = d_in[3];
    const float* Wq    = (const float*)d_in[4];
    const float* Wk    = (const float*)d_in[5];
    const float* Wv    = (const float*)d_in[6];
    const float* Wg    = (const float*)d_in[7];
    const float* bg    = (const float*)d_in[8];
    const float* Wback = (const float*)d_in[9];
    const float* bback = (const float*)d_in[10];
    const float* gamma = (const float*)d_in[11];
    const float* beta  = (const float*)d_in[12];
    float* out    = (float*)d_out;
    float* logits = out + (size_t)NN * IFZ;

    static int smem_set = 0;
    if (!smem_set) {
        cudaFuncSetAttribute(attn_mma, cudaFuncAttributeMaxDynamicSharedMemorySize,
                             ATTN_SMEMB);
        smem_set = 1;
    }

    prep_k<<<1, 256>>>(mask, batch);
    conv_ex_k<<<2048, 256>>>(emb, x);
    conv_allw_k<<<dim3(8, 16, 3), 128>>>(Wk, Wv, Wq, Wg, Wback);
    proj_qg_mma<<<dim3(32, 16), 128>>>(bg);
    proj_kv_mma<<<dim3(64, 16), 128>>>();
    conv_v_k<<<dim3(16, HH, BBATCH), 128>>>();
    attn_mma<<<dim3(MAXT, HH), 128, ATTN_SMEMB>>>();
    addlog_k<<<2048, 256>>>(logits);
    back_mma<<<dim3(32, 4), 128>>>(x, bback);
    ln_k<<<256, 256>>>(gamma, beta, out);
}